// round 3
// baseline (speedup 1.0000x reference)
#include <cuda_runtime.h>

#define N_NODES 50000
#define IN_CH   128
#define OUT_CH  64
#define N_EDGES 800000

// Scratch for projected features h = x @ W^T  (50000 x 64 f32 = 12.8 MB)
__device__ float g_h[N_NODES * OUT_CH];

// ---------------------------------------------------------------------------
// f32x2 packed-math helpers (Blackwell FFMA2 — only reachable via PTX)
// ---------------------------------------------------------------------------
__device__ __forceinline__ unsigned long long pack2(float lo, float hi) {
    unsigned long long r;
    asm("mov.b64 %0, {%1, %2};" : "=l"(r) : "f"(lo), "f"(hi));
    return r;
}
__device__ __forceinline__ unsigned long long fma2(unsigned long long a,
                                                   unsigned long long b,
                                                   unsigned long long c) {
    unsigned long long d;
    asm("fma.rn.f32x2 %0, %1, %2, %3;" : "=l"(d) : "l"(a), "l"(b), "l"(c));
    return d;
}
__device__ __forceinline__ void unpack2(unsigned long long v, float& lo, float& hi) {
    asm("mov.b64 {%0, %1}, %2;" : "=f"(lo), "=f"(hi) : "l"(v));
}

// ---------------------------------------------------------------------------
// Kernel 1: h = x @ W^T  using packed f32x2 FMA.
// W^T staged in smem as [k][c] so channel pairs (2j, 2j+1) at one k are one
// f32x2 operand. Each thread: 2 rows x 32 channels -> 32 f32x2 accumulators;
// per k: 8 LDS.128 feed 32 FFMA2 (FFMA2-pipe bound, not LDS bound).
// ---------------------------------------------------------------------------
__global__ void __launch_bounds__(256, 2) gemm_kernel(
    const float* __restrict__ x,
    const float* __restrict__ W)
{
    __shared__ float Wt[IN_CH][OUT_CH];   // 32 KB, transposed W

    for (int i = threadIdx.x; i < OUT_CH * IN_CH; i += 256) {
        int c = i >> 7;        // W is [64][128] row-major
        int k = i & 127;
        Wt[k][c] = W[i];
    }
    __syncthreads();

    int tid   = threadIdx.x;
    int chalf = tid & 1;                       // which 32-channel half
    int rp    = blockIdx.x * 128 + (tid >> 1); // row-pair id
    if (rp >= N_NODES / 2) return;
    int row0  = rp * 2;

    unsigned long long acc0[16], acc1[16];
#pragma unroll
    for (int j = 0; j < 16; j++) { acc0[j] = 0ull; acc1[j] = 0ull; }

    const float4* xr0 = reinterpret_cast<const float4*>(x + (size_t)row0 * IN_CH);
    const float4* xr1 = reinterpret_cast<const float4*>(x + (size_t)(row0 + 1) * IN_CH);
    const int cbase = chalf * 32;

#pragma unroll 2
    for (int k4 = 0; k4 < IN_CH / 4; k4++) {
        float4 xv0 = __ldg(xr0 + k4);
        float4 xv1 = __ldg(xr1 + k4);
        float x0a[4] = {xv0.x, xv0.y, xv0.z, xv0.w};
        float x1a[4] = {xv1.x, xv1.y, xv1.z, xv1.w};
#pragma unroll
        for (int kk = 0; kk < 4; kk++) {
            int k = k4 * 4 + kk;
            unsigned long long xb0 = pack2(x0a[kk], x0a[kk]);
            unsigned long long xb1 = pack2(x1a[kk], x1a[kk]);
            const float4* wr = reinterpret_cast<const float4*>(&Wt[k][cbase]);
#pragma unroll
            for (int j4 = 0; j4 < 8; j4++) {
                float4 w = wr[j4];                       // LDS.128, warp-uniform
                unsigned long long wlo = pack2(w.x, w.y);
                unsigned long long whi = pack2(w.z, w.w);
                acc0[2 * j4]     = fma2(xb0, wlo, acc0[2 * j4]);
                acc0[2 * j4 + 1] = fma2(xb0, whi, acc0[2 * j4 + 1]);
                acc1[2 * j4]     = fma2(xb1, wlo, acc1[2 * j4]);
                acc1[2 * j4 + 1] = fma2(xb1, whi, acc1[2 * j4 + 1]);
            }
        }
    }

    float4* h0 = reinterpret_cast<float4*>(g_h + (size_t)row0 * OUT_CH + cbase);
    float4* h1 = reinterpret_cast<float4*>(g_h + (size_t)(row0 + 1) * OUT_CH + cbase);
#pragma unroll
    for (int j4 = 0; j4 < 8; j4++) {
        float4 v0, v1;
        unpack2(acc0[2 * j4],     v0.x, v0.y);
        unpack2(acc0[2 * j4 + 1], v0.z, v0.w);
        unpack2(acc1[2 * j4],     v1.x, v1.y);
        unpack2(acc1[2 * j4 + 1], v1.z, v1.w);
        h0[j4] = v0;
        h1[j4] = v1;
    }
}

// ---------------------------------------------------------------------------
// Kernel 2: out[n][c] = bias[c]   (output is poisoned by the harness)
// ---------------------------------------------------------------------------
__global__ void init_out_kernel(const float* __restrict__ bias,
                                float* __restrict__ out)
{
    int i = blockIdx.x * blockDim.x + threadIdx.x;
    if (i < N_NODES * OUT_CH)
        out[i] = __ldg(bias + (i & (OUT_CH - 1)));
}

// ---------------------------------------------------------------------------
// Kernel 3: out[dst] += h[src]  for every edge.
// 16 threads per edge, float4 gather + red.global.add.v4.f32 (REDG.128).
// edge_index is int32 on device (JAX x64 disabled demotes int64 -> int32).
// ---------------------------------------------------------------------------
__global__ void __launch_bounds__(256) scatter_kernel(
    const int* __restrict__ ei,   // [2, N_EDGES] int32
    float* __restrict__ out)
{
    int t  = blockIdx.x * blockDim.x + threadIdx.x;
    int e  = t >> 4;           // edge id
    int c4 = t & 15;           // which float4 of the 64-ch row
    if (e >= N_EDGES) return;

    int src = __ldg(ei + e);
    int dst = __ldg(ei + N_EDGES + e);

    const float4* hrow = reinterpret_cast<const float4*>(g_h + (size_t)src * OUT_CH);
    float4 v = __ldg(hrow + c4);

    float* o = out + (size_t)dst * OUT_CH + c4 * 4;
    asm volatile("red.global.add.v4.f32 [%0], {%1, %2, %3, %4};"
                 :: "l"(o), "f"(v.x), "f"(v.y), "f"(v.z), "f"(v.w)
                 : "memory");
}

// ---------------------------------------------------------------------------
// Launch
// ---------------------------------------------------------------------------
extern "C" void kernel_launch(void* const* d_in, const int* in_sizes, int n_in,
                              void* d_out, int out_size)
{
    const float* x    = (const float*)d_in[0];      // [50000, 128] f32
    const int*   ei   = (const int*)d_in[1];        // [2, 800000] i32
    const float* W    = (const float*)d_in[2];      // [64, 128] f32
    const float* bias = (const float*)d_in[3];      // [64] f32
    float*       out  = (float*)d_out;              // [50000, 64] f32

    (void)in_sizes; (void)n_in; (void)out_size;

    // out = bias (independent of gemm; do it first)
    init_out_kernel<<<(N_NODES * OUT_CH + 255) / 256, 256>>>(bias, out);

    // h = x @ W^T  (196 blocks x 256 threads, 2 rows x 32 ch per thread)
    gemm_kernel<<<(N_NODES / 2 + 127) / 128, 256>>>(x, W);

    // out[dst] += h[src]
    int total_threads = N_EDGES * 16;
    scatter_kernel<<<total_threads / 256, 256>>>(ei, out);
}

// round 4
// speedup vs baseline: 1.1536x; 1.1536x over previous
#include <cuda_runtime.h>

#define N_NODES 50000
#define IN_CH   128
#define OUT_CH  64
#define N_EDGES 800000

#define SCAN_BLK   1024
#define N_SCAN_BLK ((N_NODES + SCAN_BLK - 1) / SCAN_BLK)   // 49

// Scratch (device globals — no allocation allowed)
__device__ float g_h[N_NODES * OUT_CH];       // projected features, 12.8 MB
__device__ int   g_cnt[N_NODES];              // per-dst edge counts
__device__ int   g_ofs[N_NODES + 1];          // CSR row offsets
__device__ int   g_cur[N_NODES];              // fill cursors
__device__ int   g_srcs[N_EDGES];             // src ids grouped by dst
__device__ int   g_bsum[N_SCAN_BLK];          // scan block totals
__device__ int   g_bbase[64];                 // scanned block bases

// ---------------------------------------------------------------------------
// Kernel 1: h = x @ W^T   (fp32, W staged in smem)
// Each row split across 2 threads (32 channels each) for 2x warp count vs R2.
// Warp layout: lanes 0-15 = channels 0-31 of rows r..r+15, lanes 16-31 = the
// same rows' channels 32-63 (LDS broadcast within each half-warp).
// ---------------------------------------------------------------------------
__global__ void __launch_bounds__(128) gemm_kernel(
    const float* __restrict__ x,
    const float* __restrict__ W)
{
    __shared__ float4 Ws4[OUT_CH * IN_CH / 4];  // 32 KB: Ws4[c*32 + k4]

    const float4* Wg = reinterpret_cast<const float4*>(W);
    for (int i = threadIdx.x; i < OUT_CH * IN_CH / 4; i += 128)
        Ws4[i] = Wg[i];
    __syncthreads();

    int wid  = threadIdx.x >> 5;
    int lane = threadIdx.x & 31;
    int row  = blockIdx.x * 64 + wid * 16 + (lane & 15);
    int cbase = (lane >> 4) * 32;
    if (row >= N_NODES) return;

    float acc[32];
#pragma unroll
    for (int j = 0; j < 32; j++) acc[j] = 0.0f;

    const float4* xr = reinterpret_cast<const float4*>(x + (size_t)row * IN_CH);

#pragma unroll 4
    for (int k4 = 0; k4 < IN_CH / 4; k4++) {
        float4 xv = __ldg(xr + k4);
#pragma unroll
        for (int j = 0; j < 32; j++) {
            float4 w = Ws4[(cbase + j) * (IN_CH / 4) + k4];
            acc[j] = fmaf(xv.x, w.x, acc[j]);
            acc[j] = fmaf(xv.y, w.y, acc[j]);
            acc[j] = fmaf(xv.z, w.z, acc[j]);
            acc[j] = fmaf(xv.w, w.w, acc[j]);
        }
    }

    float4* hr = reinterpret_cast<float4*>(g_h + (size_t)row * OUT_CH + cbase);
#pragma unroll
    for (int j4 = 0; j4 < 8; j4++)
        hr[j4] = make_float4(acc[4 * j4 + 0], acc[4 * j4 + 1],
                             acc[4 * j4 + 2], acc[4 * j4 + 3]);
}

// ---------------------------------------------------------------------------
// CSR build pipeline
// ---------------------------------------------------------------------------
__global__ void zero_cnt_kernel()
{
    int i = blockIdx.x * blockDim.x + threadIdx.x;
    if (i < N_NODES) g_cnt[i] = 0;
}

__global__ void count_kernel(const int* __restrict__ ei)
{
    int e = blockIdx.x * blockDim.x + threadIdx.x;
    if (e < N_EDGES)
        atomicAdd(&g_cnt[__ldg(ei + N_EDGES + e)], 1);
}

// per-block inclusive scan -> exclusive offsets + block totals
__global__ void __launch_bounds__(SCAN_BLK) scan1_kernel()
{
    __shared__ int s[SCAN_BLK];
    int tid = threadIdx.x;
    int i = blockIdx.x * SCAN_BLK + tid;
    int v = (i < N_NODES) ? g_cnt[i] : 0;
    s[tid] = v;
    __syncthreads();
#pragma unroll
    for (int d = 1; d < SCAN_BLK; d <<= 1) {
        int t = (tid >= d) ? s[tid - d] : 0;
        __syncthreads();
        s[tid] += t;
        __syncthreads();
    }
    if (i < N_NODES) g_ofs[i] = s[tid] - v;           // exclusive within block
    if (tid == SCAN_BLK - 1) g_bsum[blockIdx.x] = s[tid];
}

// scan the 49 block totals (single block)
__global__ void scan2_kernel()
{
    __shared__ int s[64];
    int tid = threadIdx.x;
    int v = (tid < N_SCAN_BLK) ? g_bsum[tid] : 0;
    s[tid] = v;
    __syncthreads();
#pragma unroll
    for (int d = 1; d < 64; d <<= 1) {
        int t = (tid >= d) ? s[tid - d] : 0;
        __syncthreads();
        s[tid] += t;
        __syncthreads();
    }
    g_bbase[tid] = s[tid] - v;                        // exclusive block base
}

// add block bases, init cursors, set final offset
__global__ void __launch_bounds__(SCAN_BLK) scan3_kernel()
{
    int i = blockIdx.x * SCAN_BLK + threadIdx.x;
    if (i < N_NODES) {
        int o = g_ofs[i] + g_bbase[blockIdx.x];
        g_ofs[i] = o;
        g_cur[i] = o;
    }
    if (i == 0) g_ofs[N_NODES] = N_EDGES;
}

// bin src ids by dst
__global__ void fill_kernel(const int* __restrict__ ei)
{
    int e = blockIdx.x * blockDim.x + threadIdx.x;
    if (e >= N_EDGES) return;
    int src = __ldg(ei + e);
    int dst = __ldg(ei + N_EDGES + e);
    int pos = atomicAdd(&g_cur[dst], 1);
    g_srcs[pos] = src;
}

// ---------------------------------------------------------------------------
// Aggregate: out[n] = bias + sum_{e in CSR row n} h[src_e]
// 16 threads per node, one float4 (4 channels) each. No atomics, no init.
// ---------------------------------------------------------------------------
__global__ void __launch_bounds__(256) aggregate_kernel(
    const float* __restrict__ bias,
    float* __restrict__ out)
{
    int t    = blockIdx.x * blockDim.x + threadIdx.x;
    int node = t >> 4;
    int c4   = t & 15;
    if (node >= N_NODES) return;

    int beg = __ldg(g_ofs + node);
    int end = __ldg(g_ofs + node + 1);

    float4 acc = __ldg(reinterpret_cast<const float4*>(bias) + c4);

    int e = beg;
    // unroll by 2 for MLP on the gather stream
    for (; e + 1 < end; e += 2) {
        int s0 = __ldg(g_srcs + e);
        int s1 = __ldg(g_srcs + e + 1);
        float4 v0 = __ldg(reinterpret_cast<const float4*>(g_h + (size_t)s0 * OUT_CH) + c4);
        float4 v1 = __ldg(reinterpret_cast<const float4*>(g_h + (size_t)s1 * OUT_CH) + c4);
        acc.x += v0.x + v1.x;
        acc.y += v0.y + v1.y;
        acc.z += v0.z + v1.z;
        acc.w += v0.w + v1.w;
    }
    if (e < end) {
        int s0 = __ldg(g_srcs + e);
        float4 v0 = __ldg(reinterpret_cast<const float4*>(g_h + (size_t)s0 * OUT_CH) + c4);
        acc.x += v0.x; acc.y += v0.y; acc.z += v0.z; acc.w += v0.w;
    }

    reinterpret_cast<float4*>(out + (size_t)node * OUT_CH)[c4] = acc;
}

// ---------------------------------------------------------------------------
// Launch
// ---------------------------------------------------------------------------
extern "C" void kernel_launch(void* const* d_in, const int* in_sizes, int n_in,
                              void* d_out, int out_size)
{
    const float* x    = (const float*)d_in[0];      // [50000, 128] f32
    const int*   ei   = (const int*)d_in[1];        // [2, 800000] i32
    const float* W    = (const float*)d_in[2];      // [64, 128] f32
    const float* bias = (const float*)d_in[3];      // [64] f32
    float*       out  = (float*)d_out;              // [50000, 64] f32

    (void)in_sizes; (void)n_in; (void)out_size;

    // CSR build (independent of GEMM)
    zero_cnt_kernel<<<(N_NODES + 255) / 256, 256>>>();
    count_kernel<<<(N_EDGES + 255) / 256, 256>>>(ei);
    scan1_kernel<<<N_SCAN_BLK, SCAN_BLK>>>();
    scan2_kernel<<<1, 64>>>();
    scan3_kernel<<<N_SCAN_BLK, SCAN_BLK>>>();
    fill_kernel<<<(N_EDGES + 255) / 256, 256>>>(ei);

    // h = x @ W^T   (782 blocks x 128 threads; 64 rows per block)
    gemm_kernel<<<(N_NODES + 63) / 64, 128>>>(x, W);

    // out = bias + segment_sum(h[src], dst)
    aggregate_kernel<<<(N_NODES * 16 + 255) / 256, 256>>>(bias, out);
}